// round 4
// baseline (speedup 1.0000x reference)
#include <cuda_runtime.h>

#define HH 512
#define WW 512
#define NB 16
#define HW (HH * WW)
#define NPIX (NB * HW)

#define EPS 0.0078125f               // 2^-7
#define SCALE (512.0f / 511.0f)      // H/(H-1)

// Tile geometry for the step kernel
#define TW 64
#define TH 16
#define MLO 5                         // low-side halo margin
#define SW 76                         // TW + 12 (5 low + 7 high)
#define SH 27                         // TH + 11 (5 low + 6 high)
#define SMN (SW * SH)

// Ping-pong scratch (allocation-free per harness rules)
static __device__ float2 g_dispA[NB * HW];
static __device__ float2 g_dispB[NB * HW];
static __device__ float  g_ldA[NB * HW];
static __device__ float  g_ldB[NB * HW];

// ---------------------------------------------------------------------------
// Zero-padded global taps (rare fallback path)
// ---------------------------------------------------------------------------
__device__ __forceinline__ float tap1(const float* __restrict__ s, int y, int x) {
    return ((unsigned)x < (unsigned)WW && (unsigned)y < (unsigned)HH)
               ? __ldg(s + y * WW + x) : 0.0f;
}
__device__ __forceinline__ float2 tap2(const float2* __restrict__ s, int y, int x) {
    return ((unsigned)x < (unsigned)WW && (unsigned)y < (unsigned)HH)
               ? __ldg(s + y * WW + x) : make_float2(0.0f, 0.0f);
}

// ---------------------------------------------------------------------------
// Init: disp0 = eps*vel (interleaved) ; ldjac0 via Newton identities on
// the 2x2 Sobel Jacobian (tr(J^n) from t=tr, s=det).
// ---------------------------------------------------------------------------
__global__ __launch_bounds__(256) void init_kernel(const float* __restrict__ vel,
                                                   float2* __restrict__ disp,
                                                   float* __restrict__ ld) {
    int idx = blockIdx.x * blockDim.x + threadIdx.x;
    if (idx >= NPIX) return;
    int n = idx >> 18;            // / HW
    int p = idx & (HW - 1);
    int y = p >> 9;               // / WW
    int x = p & (WW - 1);

    const float* v0 = vel + (size_t)n * 2 * HW;   // vel_y plane
    const float* v1 = v0 + HW;                    // vel_x plane

    disp[(size_t)n * HW + p] = make_float2(EPS * __ldg(v0 + p), EPS * __ldg(v1 + p));

    int ym = max(y - 1, 0), yp = min(y + 1, HH - 1);
    int xm = max(x - 1, 0), xp = min(x + 1, WW - 1);
    int rm = ym * WW, rc = y * WW, rp = yp * WW;

    float a00 = __ldg(v0 + rm + xm), a01 = __ldg(v0 + rm + x), a02 = __ldg(v0 + rm + xp);
    float a10 = __ldg(v0 + rc + xm),                           a12 = __ldg(v0 + rc + xp);
    float a20 = __ldg(v0 + rp + xm), a21 = __ldg(v0 + rp + x), a22 = __ldg(v0 + rp + xp);

    float c00 = __ldg(v1 + rm + xm), c01 = __ldg(v1 + rm + x), c02 = __ldg(v1 + rm + xp);
    float c10 = __ldg(v1 + rc + xm),                           c12 = __ldg(v1 + rc + xp);
    float c20 = __ldg(v1 + rp + xm), c21 = __ldg(v1 + rp + x), c22 = __ldg(v1 + rp + xp);

    float J00 = 0.125f * ((a20 + 2.0f * a21 + a22) - (a00 + 2.0f * a01 + a02));
    float J01 = 0.125f * ((a02 + 2.0f * a12 + a22) - (a00 + 2.0f * a10 + a20));
    float J10 = 0.125f * ((c20 + 2.0f * c21 + c22) - (c00 + 2.0f * c01 + c02));
    float J11 = 0.125f * ((c02 + 2.0f * c12 + c22) - (c00 + 2.0f * c10 + c20));

    float t = J00 + J11;
    float s = J00 * J11 - J01 * J10;
    float p1 = t;
    float p2 = t * t - 2.0f * s;
    float p3 = t * (t * t - 3.0f * s);
    float p4 = t * t * (t * t - 4.0f * s) + 2.0f * s * s;

    const float e2 = EPS * EPS, e3 = e2 * EPS, e4 = e2 * e2;
    ld[(size_t)n * HW + p] = EPS * p1 - 0.5f * e2 * p2 + (e3 / 3.0f) * p3 - 0.25f * e4 * p4;
}

// ---------------------------------------------------------------------------
// One squaring step: smem-tiled gathers. 1024 threads, 64x16 tile, 1 px/thread.
// FINAL=true writes planar layout into d_out.
// ---------------------------------------------------------------------------
template <bool FINAL>
__global__ __launch_bounds__(1024, 2)
void step_kernel(const float2* __restrict__ dispIn,
                 const float*  __restrict__ ldIn,
                 float2* __restrict__ dispOut,   // !FINAL
                 float*  __restrict__ ldOut,     // !FINAL
                 float*  __restrict__ outBuf) {  // FINAL
    __shared__ float2 sd[SMN];
    __shared__ float  sl[SMN];

    int n   = blockIdx.z;
    int gx0 = blockIdx.x * TW;
    int gy0 = blockIdx.y * TH;

    const float2* d = dispIn + (size_t)n * HW;
    const float*  l = ldIn   + (size_t)n * HW;

    int tid = threadIdx.y * TW + threadIdx.x;

    // ---- stage tile + halo into smem (zero outside image = zero padding) ----
    for (int e = tid; e < SMN; e += 1024) {
        int r = e / SW;
        int c = e - r * SW;
        int gy = gy0 - MLO + r;
        int gx = gx0 - MLO + c;
        bool in = ((unsigned)gx < (unsigned)WW) & ((unsigned)gy < (unsigned)HH);
        int gp = gy * WW + gx;
        sd[e] = in ? __ldg(d + gp) : make_float2(0.0f, 0.0f);
        sl[e] = in ? __ldg(l + gp) : 0.0f;
    }
    __syncthreads();

    // ---- compute one pixel ----
    int x = gx0 + threadIdx.x;
    int y = gy0 + threadIdx.y;
    int p = y * WW + x;
    int sci = (threadIdx.y + MLO) * SW + (threadIdx.x + MLO);

    float2 c0 = sd[sci];
    float dy0 = c0.x, dx0 = c0.y;

    // sample disp at its own warped location
    float sy = ((float)y + dy0) * SCALE - 0.5f;
    float sx = ((float)x + dx0) * SCALE - 0.5f;
    float xf = floorf(sx), yf = floorf(sy);
    float wx = sx - xf, wy = sy - yf;
    int x0 = (int)xf, y0 = (int)yf;
    int sxi = x0 - gx0 + MLO;
    int syi = y0 - gy0 + MLO;

    float2 v00, v01, v10, v11;
    if ((unsigned)sxi < (unsigned)(SW - 1) && (unsigned)syi < (unsigned)(SH - 1)) {
        const float2* r0 = sd + syi * SW + sxi;
        v00 = r0[0]; v01 = r0[1]; v10 = r0[SW]; v11 = r0[SW + 1];
    } else {
        v00 = tap2(d, y0, x0);     v01 = tap2(d, y0, x0 + 1);
        v10 = tap2(d, y0 + 1, x0); v11 = tap2(d, y0 + 1, x0 + 1);
    }
    float ax = v00.x + wx * (v01.x - v00.x);
    float bx = v10.x + wx * (v11.x - v10.x);
    float ay = v00.y + wx * (v01.y - v00.y);
    float by = v10.y + wx * (v11.y - v10.y);
    float ndy = dy0 + (ax + wy * (bx - ax));
    float ndx = dx0 + (ay + wy * (by - ay));

    // ---- ldjac: warp by NEW displacement ----
    float sy2 = ((float)y + ndy) * SCALE - 0.5f;
    float sx2 = ((float)x + ndx) * SCALE - 0.5f;
    float xf2 = floorf(sx2), yf2 = floorf(sy2);
    float wx2 = sx2 - xf2, wy2 = sy2 - yf2;
    int x2 = (int)xf2, y2 = (int)yf2;
    int sxi2 = x2 - gx0 + MLO;
    int syi2 = y2 - gy0 + MLO;

    float u00, u01, u10, u11;
    if ((unsigned)sxi2 < (unsigned)(SW - 1) && (unsigned)syi2 < (unsigned)(SH - 1)) {
        const float* r0 = sl + syi2 * SW + sxi2;
        u00 = r0[0]; u01 = r0[1]; u10 = r0[SW]; u11 = r0[SW + 1];
    } else {
        u00 = tap1(l, y2, x2);     u01 = tap1(l, y2, x2 + 1);
        u10 = tap1(l, y2 + 1, x2); u11 = tap1(l, y2 + 1, x2 + 1);
    }
    float la = u00 + wx2 * (u01 - u00);
    float lb = u10 + wx2 * (u11 - u10);
    float nl = sl[sci] + (la + wy2 * (lb - la));

    // ---- stores ----
    if (FINAL) {
        float* od = outBuf + (size_t)n * 2 * HW;
        od[p]      = ndy;
        od[HW + p] = ndx;
        outBuf[(size_t)NB * 2 * HW + (size_t)n * HW + p] = nl;
    } else {
        dispOut[(size_t)n * HW + p] = make_float2(ndy, ndx);
        ldOut[(size_t)n * HW + p]   = nl;
    }
}

// ---------------------------------------------------------------------------
extern "C" void kernel_launch(void* const* d_in, const int* in_sizes, int n_in,
                              void* d_out, int out_size) {
    const float* vel = (const float*)d_in[0];
    float* out = (float*)d_out;

    float2 *dA, *dB;
    float *lA, *lB;
    cudaGetSymbolAddress((void**)&dA, g_dispA);
    cudaGetSymbolAddress((void**)&dB, g_dispB);
    cudaGetSymbolAddress((void**)&lA, g_ldA);
    cudaGetSymbolAddress((void**)&lB, g_ldB);

    const int threadsInit = 256;
    const int blocksInit = (NPIX + threadsInit - 1) / threadsInit;
    init_kernel<<<blocksInit, threadsInit>>>(vel, dA, lA);

    dim3 sblock(TW, TH);                       // 1024 threads
    dim3 sgrid(WW / TW, HH / TH, NB);          // 8 x 32 x 16

    step_kernel<false><<<sgrid, sblock>>>(dA, lA, dB, lB, nullptr);  // 1
    step_kernel<false><<<sgrid, sblock>>>(dB, lB, dA, lA, nullptr);  // 2
    step_kernel<false><<<sgrid, sblock>>>(dA, lA, dB, lB, nullptr);  // 3
    step_kernel<false><<<sgrid, sblock>>>(dB, lB, dA, lA, nullptr);  // 4
    step_kernel<false><<<sgrid, sblock>>>(dA, lA, dB, lB, nullptr);  // 5
    step_kernel<false><<<sgrid, sblock>>>(dB, lB, dA, lA, nullptr);  // 6
    step_kernel<true><<<sgrid, sblock>>>(dA, lA, nullptr, nullptr, out);  // 7
}

// round 5
// speedup vs baseline: 1.2731x; 1.2731x over previous
#include <cuda_runtime.h>

#define HH 512
#define WW 512
#define NB 16
#define HW (HH * WW)
#define NPIX (NB * HW)

#define EPS 0.0078125f               // 2^-7
#define SCALE (512.0f / 511.0f)      // H/(H-1)

// Scratch: disp interleaved (float2/px), ld scalar. Ping-pong.
static __device__ float2 g_dispA[NB * HW];
static __device__ float2 g_dispB[NB * HW];
static __device__ float  g_ldA[NB * HW];
static __device__ float  g_ldB[NB * HW];

// ---------------------------------------------------------------------------
// Zero-padded taps (rare fallback)
// ---------------------------------------------------------------------------
__device__ __forceinline__ float tap1(const float* __restrict__ s, int y, int x) {
    return ((unsigned)x < (unsigned)WW && (unsigned)y < (unsigned)HH)
               ? __ldg(s + y * WW + x) : 0.0f;
}
__device__ __forceinline__ float2 tap2(const float2* __restrict__ s, int y, int x) {
    return ((unsigned)x < (unsigned)WW && (unsigned)y < (unsigned)HH)
               ? __ldg(s + y * WW + x) : make_float2(0.0f, 0.0f);
}

__device__ __forceinline__ float bilin1(const float* __restrict__ s, float sx, float sy) {
    int x0 = __float2int_rd(sx), y0 = __float2int_rd(sy);
    float wx = sx - (float)x0, wy = sy - (float)y0;
    float v00, v01, v10, v11;
    if ((unsigned)x0 < (unsigned)(WW - 1) && (unsigned)y0 < (unsigned)(HH - 1)) {
        const float* r = s + y0 * WW + x0;
        v00 = __ldg(r); v01 = __ldg(r + 1); v10 = __ldg(r + WW); v11 = __ldg(r + WW + 1);
    } else {
        v00 = tap1(s, y0, x0);     v01 = tap1(s, y0, x0 + 1);
        v10 = tap1(s, y0 + 1, x0); v11 = tap1(s, y0 + 1, x0 + 1);
    }
    float a = v00 + wx * (v01 - v00);
    float b = v10 + wx * (v11 - v10);
    return a + wy * (b - a);
}

__device__ __forceinline__ float2 bilin2i(const float2* __restrict__ s, float sx, float sy) {
    int x0 = __float2int_rd(sx), y0 = __float2int_rd(sy);
    float wx = sx - (float)x0, wy = sy - (float)y0;
    float2 v00, v01, v10, v11;
    if ((unsigned)x0 < (unsigned)(WW - 1) && (unsigned)y0 < (unsigned)(HH - 1)) {
        const float2* r = s + y0 * WW + x0;
        v00 = __ldg(r); v01 = __ldg(r + 1); v10 = __ldg(r + WW); v11 = __ldg(r + WW + 1);
    } else {
        v00 = tap2(s, y0, x0);     v01 = tap2(s, y0, x0 + 1);
        v10 = tap2(s, y0 + 1, x0); v11 = tap2(s, y0 + 1, x0 + 1);
    }
    float ax = v00.x + wx * (v01.x - v00.x);
    float bx = v10.x + wx * (v11.x - v10.x);
    float ay = v00.y + wx * (v01.y - v00.y);
    float by = v10.y + wx * (v11.y - v10.y);
    return make_float2(ax + wy * (bx - ax), ay + wy * (by - ay));
}

// ---------------------------------------------------------------------------
// Init: disp0 = eps*vel (interleaved) ; ldjac0 via Newton identities.
// ---------------------------------------------------------------------------
__global__ __launch_bounds__(256) void init_kernel(const float* __restrict__ vel,
                                                   float2* __restrict__ disp,
                                                   float* __restrict__ ld) {
    int idx = blockIdx.x * blockDim.x + threadIdx.x;
    if (idx >= NPIX) return;
    int n = idx >> 18;
    int p = idx & (HW - 1);
    int y = p >> 9;
    int x = p & (WW - 1);

    const float* v0 = vel + (size_t)n * 2 * HW;
    const float* v1 = v0 + HW;

    disp[(size_t)n * HW + p] = make_float2(EPS * __ldg(v0 + p), EPS * __ldg(v1 + p));

    int ym = max(y - 1, 0), yp = min(y + 1, HH - 1);
    int xm = max(x - 1, 0), xp = min(x + 1, WW - 1);
    int rm = ym * WW, rc = y * WW, rp = yp * WW;

    float a00 = __ldg(v0 + rm + xm), a01 = __ldg(v0 + rm + x), a02 = __ldg(v0 + rm + xp);
    float a10 = __ldg(v0 + rc + xm),                           a12 = __ldg(v0 + rc + xp);
    float a20 = __ldg(v0 + rp + xm), a21 = __ldg(v0 + rp + x), a22 = __ldg(v0 + rp + xp);

    float c00 = __ldg(v1 + rm + xm), c01 = __ldg(v1 + rm + x), c02 = __ldg(v1 + rm + xp);
    float c10 = __ldg(v1 + rc + xm),                           c12 = __ldg(v1 + rc + xp);
    float c20 = __ldg(v1 + rp + xm), c21 = __ldg(v1 + rp + x), c22 = __ldg(v1 + rp + xp);

    float J00 = 0.125f * ((a20 + 2.0f * a21 + a22) - (a00 + 2.0f * a01 + a02));
    float J01 = 0.125f * ((a02 + 2.0f * a12 + a22) - (a00 + 2.0f * a10 + a20));
    float J10 = 0.125f * ((c20 + 2.0f * c21 + c22) - (c00 + 2.0f * c01 + c02));
    float J11 = 0.125f * ((c02 + 2.0f * c12 + c22) - (c00 + 2.0f * c10 + c20));

    float t = J00 + J11;
    float s = J00 * J11 - J01 * J10;
    float p1 = t;
    float p2 = t * t - 2.0f * s;
    float p3 = t * (t * t - 3.0f * s);
    float p4 = t * t * (t * t - 4.0f * s) + 2.0f * s * s;

    const float e2 = EPS * EPS, e3 = e2 * EPS, e4 = e2 * e2;
    ld[(size_t)n * HW + p] = EPS * p1 - 0.5f * e2 * p2 + (e3 / 3.0f) * p3 - 0.25f * e4 * p4;
}

// ---------------------------------------------------------------------------
// One squaring step, 4 pixels per thread (quad aligned). FINAL -> planar out.
// ---------------------------------------------------------------------------
template <bool FINAL>
__global__ __launch_bounds__(256)
void step_kernel(const float2* __restrict__ dispIn,
                 const float*  __restrict__ ldIn,
                 float2* __restrict__ dispOut,   // !FINAL
                 float*  __restrict__ ldOut,     // !FINAL
                 float*  __restrict__ outBuf) {  // FINAL
    int idx = blockIdx.x * blockDim.x + threadIdx.x;   // NPIX/4 threads
    int n = idx >> 16;                 // / (HW/4) = 2^16
    int q = idx & 65535;
    int y = q >> 7;                    // / (WW/4) = 128
    int x = (q & 127) << 2;            // quad-aligned x
    int p = (y << 9) + x;

    const float2* d = dispIn + (size_t)n * HW;
    const float*  l = ldIn   + (size_t)n * HW;

    // center loads: 2x float4 (disp pairs) + 1x float4 (ld quad)
    float4 c01 = __ldg(reinterpret_cast<const float4*>(d + p));
    float4 c23 = __ldg(reinterpret_cast<const float4*>(d + p + 2));
    float4 lc  = __ldg(reinterpret_cast<const float4*>(l + p));

    float fy = (float)y;
    float dy[4] = {c01.x, c01.z, c23.x, c23.z};
    float dx[4] = {c01.y, c01.w, c23.y, c23.w};

    float ndy[4], ndx[4], nl[4];

    // --- disp gathers (4 independent chains; compiler interleaves loads) ---
#pragma unroll
    for (int i = 0; i < 4; i++) {
        float sy = (fy + dy[i]) * SCALE - 0.5f;
        float sx = ((float)(x + i) + dx[i]) * SCALE - 0.5f;
        float2 smp = bilin2i(d, sx, sy);
        ndy[i] = dy[i] + smp.x;
        ndx[i] = dx[i] + smp.y;
    }

    // --- ld gathers at NEW displacement ---
    float lcv[4] = {lc.x, lc.y, lc.z, lc.w};
#pragma unroll
    for (int i = 0; i < 4; i++) {
        float sy = (fy + ndy[i]) * SCALE - 0.5f;
        float sx = ((float)(x + i) + ndx[i]) * SCALE - 0.5f;
        nl[i] = lcv[i] + bilin1(l, sx, sy);
    }

    // --- stores ---
    if (FINAL) {
        float* od = outBuf + (size_t)n * 2 * HW;
        *reinterpret_cast<float4*>(od + p) =
            make_float4(ndy[0], ndy[1], ndy[2], ndy[3]);
        *reinterpret_cast<float4*>(od + HW + p) =
            make_float4(ndx[0], ndx[1], ndx[2], ndx[3]);
        float* ol = outBuf + (size_t)NB * 2 * HW + (size_t)n * HW;
        *reinterpret_cast<float4*>(ol + p) =
            make_float4(nl[0], nl[1], nl[2], nl[3]);
    } else {
        float2* dout = dispOut + (size_t)n * HW;
        *reinterpret_cast<float4*>(dout + p) =
            make_float4(ndy[0], ndx[0], ndy[1], ndx[1]);
        *reinterpret_cast<float4*>(dout + p + 2) =
            make_float4(ndy[2], ndx[2], ndy[3], ndx[3]);
        *reinterpret_cast<float4*>(ldOut + (size_t)n * HW + p) =
            make_float4(nl[0], nl[1], nl[2], nl[3]);
    }
}

// ---------------------------------------------------------------------------
extern "C" void kernel_launch(void* const* d_in, const int* in_sizes, int n_in,
                              void* d_out, int out_size) {
    const float* vel = (const float*)d_in[0];
    float* out = (float*)d_out;

    float2 *dA, *dB;
    float *lA, *lB;
    cudaGetSymbolAddress((void**)&dA, g_dispA);
    cudaGetSymbolAddress((void**)&dB, g_dispB);
    cudaGetSymbolAddress((void**)&lA, g_ldA);
    cudaGetSymbolAddress((void**)&lB, g_ldB);

    const int threads = 256;
    const int blocksInit = (NPIX + threads - 1) / threads;
    const int blocksStep = (NPIX / 4) / threads;

    init_kernel<<<blocksInit, threads>>>(vel, dA, lA);
    step_kernel<false><<<blocksStep, threads>>>(dA, lA, dB, lB, nullptr);  // 1
    step_kernel<false><<<blocksStep, threads>>>(dB, lB, dA, lA, nullptr);  // 2
    step_kernel<false><<<blocksStep, threads>>>(dA, lA, dB, lB, nullptr);  // 3
    step_kernel<false><<<blocksStep, threads>>>(dB, lB, dA, lA, nullptr);  // 4
    step_kernel<false><<<blocksStep, threads>>>(dA, lA, dB, lB, nullptr);  // 5
    step_kernel<false><<<blocksStep, threads>>>(dB, lB, dA, lA, nullptr);  // 6
    step_kernel<true><<<blocksStep, threads>>>(dA, lA, nullptr, nullptr, out);  // 7
}

// round 6
// speedup vs baseline: 1.6502x; 1.2962x over previous
#include <cuda_runtime.h>

#define HH 512
#define WW 512
#define NB 16
#define HW (HH * WW)
#define NPIX (NB * HW)

#define EPS 0.0078125f               // 2^-7
#define SCALE (512.0f / 511.0f)      // H/(H-1)

// Scratch: disp interleaved (float2/px), ld scalar. Ping-pong.
static __device__ float2 g_dispA[NB * HW];
static __device__ float2 g_dispB[NB * HW];
static __device__ float  g_ldA[NB * HW];
static __device__ float  g_ldB[NB * HW];

// ---------------------------------------------------------------------------
// Branchless bilinear: clamp addresses, fold per-corner validity into weights.
// Exactly matches zero-padding semantics of the reference.
// ---------------------------------------------------------------------------
struct BilinW {
    int o00, o01, o10, o11;       // clamped offsets
    float w00, w01, w10, w11;     // masked weights
};

__device__ __forceinline__ BilinW bilin_setup(float sx, float sy) {
    int x0 = __float2int_rd(sx);
    int y0 = __float2int_rd(sy);
    float wx = sx - (float)x0;
    float wy = sy - (float)y0;
    int x1 = x0 + 1, y1 = y0 + 1;

    float mx0 = ((unsigned)x0 < (unsigned)WW) ? 1.0f : 0.0f;
    float mx1 = ((unsigned)x1 < (unsigned)WW) ? 1.0f : 0.0f;
    float my0 = ((unsigned)y0 < (unsigned)HH) ? 1.0f : 0.0f;
    float my1 = ((unsigned)y1 < (unsigned)HH) ? 1.0f : 0.0f;

    int xc0 = min(max(x0, 0), WW - 1);
    int xc1 = min(max(x1, 0), WW - 1);
    int yc0 = min(max(y0, 0), HH - 1);
    int yc1 = min(max(y1, 0), HH - 1);

    BilinW b;
    b.o00 = yc0 * WW + xc0; b.o01 = yc0 * WW + xc1;
    b.o10 = yc1 * WW + xc0; b.o11 = yc1 * WW + xc1;
    float ax0 = (1.0f - wx) * mx0, ax1 = wx * mx1;
    float ay0 = (1.0f - wy) * my0, ay1 = wy * my1;
    b.w00 = ax0 * ay0; b.w01 = ax1 * ay0;
    b.w10 = ax0 * ay1; b.w11 = ax1 * ay1;
    return b;
}

__device__ __forceinline__ float2 bilin2i(const float2* __restrict__ s, float sx, float sy) {
    BilinW b = bilin_setup(sx, sy);
    float2 v00 = __ldg(s + b.o00);
    float2 v01 = __ldg(s + b.o01);
    float2 v10 = __ldg(s + b.o10);
    float2 v11 = __ldg(s + b.o11);
    float rx = v00.x * b.w00 + v01.x * b.w01 + v10.x * b.w10 + v11.x * b.w11;
    float ry = v00.y * b.w00 + v01.y * b.w01 + v10.y * b.w10 + v11.y * b.w11;
    return make_float2(rx, ry);
}

__device__ __forceinline__ float bilin1(const float* __restrict__ s, float sx, float sy) {
    BilinW b = bilin_setup(sx, sy);
    float v00 = __ldg(s + b.o00);
    float v01 = __ldg(s + b.o01);
    float v10 = __ldg(s + b.o10);
    float v11 = __ldg(s + b.o11);
    return v00 * b.w00 + v01 * b.w01 + v10 * b.w10 + v11 * b.w11;
}

// ---------------------------------------------------------------------------
// Init: disp0 = eps*vel (interleaved) ; ldjac0 via Newton identities on
// the 2x2 Sobel Jacobian (tr(J^n) from t=tr, s=det).
// ---------------------------------------------------------------------------
__global__ __launch_bounds__(256) void init_kernel(const float* __restrict__ vel,
                                                   float2* __restrict__ disp,
                                                   float* __restrict__ ld) {
    int idx = blockIdx.x * blockDim.x + threadIdx.x;
    if (idx >= NPIX) return;
    int n = idx >> 18;
    int p = idx & (HW - 1);
    int y = p >> 9;
    int x = p & (WW - 1);

    const float* v0 = vel + (size_t)n * 2 * HW;
    const float* v1 = v0 + HW;

    disp[(size_t)n * HW + p] = make_float2(EPS * __ldg(v0 + p), EPS * __ldg(v1 + p));

    int ym = max(y - 1, 0), yp = min(y + 1, HH - 1);
    int xm = max(x - 1, 0), xp = min(x + 1, WW - 1);
    int rm = ym * WW, rc = y * WW, rp = yp * WW;

    float a00 = __ldg(v0 + rm + xm), a01 = __ldg(v0 + rm + x), a02 = __ldg(v0 + rm + xp);
    float a10 = __ldg(v0 + rc + xm),                           a12 = __ldg(v0 + rc + xp);
    float a20 = __ldg(v0 + rp + xm), a21 = __ldg(v0 + rp + x), a22 = __ldg(v0 + rp + xp);

    float c00 = __ldg(v1 + rm + xm), c01 = __ldg(v1 + rm + x), c02 = __ldg(v1 + rm + xp);
    float c10 = __ldg(v1 + rc + xm),                           c12 = __ldg(v1 + rc + xp);
    float c20 = __ldg(v1 + rp + xm), c21 = __ldg(v1 + rp + x), c22 = __ldg(v1 + rp + xp);

    float J00 = 0.125f * ((a20 + 2.0f * a21 + a22) - (a00 + 2.0f * a01 + a02));
    float J01 = 0.125f * ((a02 + 2.0f * a12 + a22) - (a00 + 2.0f * a10 + a20));
    float J10 = 0.125f * ((c20 + 2.0f * c21 + c22) - (c00 + 2.0f * c01 + c02));
    float J11 = 0.125f * ((c02 + 2.0f * c12 + c22) - (c00 + 2.0f * c10 + c20));

    float t = J00 + J11;
    float s = J00 * J11 - J01 * J10;
    float p1 = t;
    float p2 = t * t - 2.0f * s;
    float p3 = t * (t * t - 3.0f * s);
    float p4 = t * t * (t * t - 4.0f * s) + 2.0f * s * s;

    const float e2 = EPS * EPS, e3 = e2 * EPS, e4 = e2 * e2;
    ld[(size_t)n * HW + p] = EPS * p1 - 0.5f * e2 * p2 + (e3 / 3.0f) * p3 - 0.25f * e4 * p4;
}

// ---------------------------------------------------------------------------
// One squaring step, 2 pixels per thread, fully branchless gathers.
// FINAL=true writes planar layout into d_out.
// ---------------------------------------------------------------------------
template <bool FINAL>
__global__ __launch_bounds__(256)
void step_kernel(const float2* __restrict__ dispIn,
                 const float*  __restrict__ ldIn,
                 float2* __restrict__ dispOut,   // !FINAL
                 float*  __restrict__ ldOut,     // !FINAL
                 float*  __restrict__ outBuf) {  // FINAL
    int idx = blockIdx.x * blockDim.x + threadIdx.x;   // NPIX/2 threads
    int n  = idx >> 17;                 // / (HW/2)
    int p2 = idx & (HW / 2 - 1);
    int y  = p2 >> 8;                   // / (WW/2)
    int x  = (p2 & 255) << 1;           // even x
    int p  = (y << 9) + x;

    const float2* d = dispIn + (size_t)n * HW;
    const float*  l = ldIn   + (size_t)n * HW;

    // center disp pair: one 16B load; center ld pair: one 8B load
    float4 c = __ldg(reinterpret_cast<const float4*>(d + p));
    float2 lc = __ldg(reinterpret_cast<const float2*>(l + p));
    float dy0 = c.x, dx0 = c.y, dy1 = c.z, dx1 = c.w;

    float fy = (float)y;

    // --- disp gathers (branchless; loads batch) ---
    float2 s0 = bilin2i(d, ((float)x + dx0) * SCALE - 0.5f,
                           (fy + dy0) * SCALE - 0.5f);
    float2 s1 = bilin2i(d, ((float)(x + 1) + dx1) * SCALE - 0.5f,
                           (fy + dy1) * SCALE - 0.5f);
    float ndy0 = dy0 + s0.x, ndx0 = dx0 + s0.y;
    float ndy1 = dy1 + s1.x, ndx1 = dx1 + s1.y;

    // --- ldjac gathers at NEW displacement ---
    float ls0 = bilin1(l, ((float)x + ndx0) * SCALE - 0.5f,
                          (fy + ndy0) * SCALE - 0.5f);
    float ls1 = bilin1(l, ((float)(x + 1) + ndx1) * SCALE - 0.5f,
                          (fy + ndy1) * SCALE - 0.5f);
    float nl0 = lc.x + ls0, nl1 = lc.y + ls1;

    // --- stores ---
    if (FINAL) {
        float* od = outBuf + (size_t)n * 2 * HW;
        *reinterpret_cast<float2*>(od + p)      = make_float2(ndy0, ndy1);
        *reinterpret_cast<float2*>(od + HW + p) = make_float2(ndx0, ndx1);
        float* ol = outBuf + (size_t)NB * 2 * HW + (size_t)n * HW;
        *reinterpret_cast<float2*>(ol + p) = make_float2(nl0, nl1);
    } else {
        *reinterpret_cast<float4*>(dispOut + (size_t)n * HW + p) =
            make_float4(ndy0, ndx0, ndy1, ndx1);
        *reinterpret_cast<float2*>(ldOut + (size_t)n * HW + p) = make_float2(nl0, nl1);
    }
}

// ---------------------------------------------------------------------------
extern "C" void kernel_launch(void* const* d_in, const int* in_sizes, int n_in,
                              void* d_out, int out_size) {
    const float* vel = (const float*)d_in[0];
    float* out = (float*)d_out;

    float2 *dA, *dB;
    float *lA, *lB;
    cudaGetSymbolAddress((void**)&dA, g_dispA);
    cudaGetSymbolAddress((void**)&dB, g_dispB);
    cudaGetSymbolAddress((void**)&lA, g_ldA);
    cudaGetSymbolAddress((void**)&lB, g_ldB);

    const int threads = 256;
    const int blocksInit = (NPIX + threads - 1) / threads;
    const int blocksStep = (NPIX / 2) / threads;

    init_kernel<<<blocksInit, threads>>>(vel, dA, lA);
    step_kernel<false><<<blocksStep, threads>>>(dA, lA, dB, lB, nullptr);  // 1
    step_kernel<false><<<blocksStep, threads>>>(dB, lB, dA, lA, nullptr);  // 2
    step_kernel<false><<<blocksStep, threads>>>(dA, lA, dB, lB, nullptr);  // 3
    step_kernel<false><<<blocksStep, threads>>>(dB, lB, dA, lA, nullptr);  // 4
    step_kernel<false><<<blocksStep, threads>>>(dA, lA, dB, lB, nullptr);  // 5
    step_kernel<false><<<blocksStep, threads>>>(dB, lB, dA, lA, nullptr);  // 6
    step_kernel<true><<<blocksStep, threads>>>(dA, lA, nullptr, nullptr, out);  // 7
}